// round 15
// baseline (speedup 1.0000x reference)
#include <cuda_runtime.h>
#include <cuda_fp16.h>

// retinex_synthesis: out = clip(expm1(log1p(ins) + blur(log1p(bg) - log1p(ins))), 0, 1)
// blur = depthwise 31x31 Gaussian (sigma=5), separable.
// Algebra:  blur(bg_log)-blur(ins_log) = blur(d2), d2 = log2(1+bg)-log2(1+ins)
//           out = (1+ins) * 2^blur(d2) - 1
// K1: horizontal 31-tap on d2 -> fp16 temp (evict-last stores). 8 rows/block:
//     8 independent LDG.128 per thread (MLP=8) to push streaming BW.
// K2: vertical 31-tap in HFMA2, smem-staged 46-row slab; out stores carry an
//     evict-first hint (never re-read; keeps temp/ins resident).

static constexpr int Wd    = 512;
static constexpr int Hd    = 512;
static constexpr int NIMG  = 48;                // B*C = 16*3
static constexpr int NPIX  = NIMG * Hd * Wd;    // 12,582,912
static constexpr int NROWS = NIMG * Hd;         // 24,576

__device__ __align__(16) __half2 g_temp2[NPIX / 2];   // 25.2 MB scratch

// Normalized 1D Gaussian, sigma=5, 31 taps (double-derived literals).
#define GW_LIST { \
    8.8805900e-4f, 1.5860940e-3f, 2.7217700e-3f, 4.4874400e-3f, 7.1084370e-3f, \
    1.0818768e-2f, 1.5820117e-2f, 2.2226435e-2f, 3.0002550e-2f, 3.8911210e-2f, \
    4.8486353e-2f, 5.8048703e-2f, 6.6771903e-2f, 7.3794366e-2f, 7.8357554e-2f, \
    7.9940482e-2f, \
    7.8357554e-2f, 7.3794366e-2f, 6.6771903e-2f, 5.8048703e-2f, 4.8486353e-2f, \
    3.8911210e-2f, 3.0002550e-2f, 2.2226435e-2f, 1.5820117e-2f, 1.0818768e-2f, \
    7.1084370e-3f, 4.4874400e-3f, 2.7217700e-3f, 1.5860940e-3f, 8.8805900e-4f }

__device__ __forceinline__ float ex2(float x) {        // MUFU.EX2
    float r; asm("ex2.approx.ftz.f32 %0, %1;" : "=f"(r) : "f"(x)); return r;
}
__device__ __forceinline__ float dlog2(float b, float i) {   // log2(1+b)-log2(1+i)
    return __log2f(1.0f + b) - __log2f(1.0f + i);
}
__device__ __forceinline__ unsigned h2u(__half2 h) {
    union { __half2 h; unsigned u; } c; c.h = h; return c.u;
}

// ---------------------------------------------------------------------------
// K1: horizontal blur of d2. One block = 8 rows (4096 floats), MLP=8.
// ---------------------------------------------------------------------------
__global__ void __launch_bounds__(256) k_hblur(const float* __restrict__ bg,
                                               const float* __restrict__ ins) {
    const float w[31] = GW_LIST;
    __shared__ __align__(16) float s[8][544];   // [0..15]=0 | data | [528..543]=0

    const int tid = threadIdx.x;
    {   // zero pads: 8 rows x 32 slots = 256
        const int r = tid >> 5, p = tid & 31;
        s[r][(p < 16) ? p : (512 + p)] = 0.0f;
    }

    const size_t gb = (size_t)blockIdx.x * 1024;        // float4 units (8 rows)
    const float4* bg4 = (const float4*)bg;
    const float4* in4 = (const float4*)ins;

#pragma unroll
    for (int h = 0; h < 4; h++) {
        const int q = tid + h * 256;                    // f4 idx in block: 0..1023
        const float4 b = __ldcs(bg4 + gb + q);          // bg: stream, evict-first
        const float4 i = in4[gb + q];                   // ins: plain
        const int row = q >> 7, col = (q & 127) * 4;
        *(float4*)&s[row][16 + col] =
            make_float4(dlog2(b.x, i.x), dlog2(b.y, i.y),
                        dlog2(b.z, i.z), dlog2(b.w, i.w));
    }
    __syncthreads();

    const int row = tid >> 5;             // 0..7 (32 threads per row)
    unsigned long long pol;
    asm("createpolicy.fractional.L2::evict_last.b64 %0, 1.0;" : "=l"(pol));

#pragma unroll
    for (int seg = 0; seg < 2; seg++) {
        const int col = (tid & 31) * 16 + seg * 8;      // 0..504

        float v[40];
#pragma unroll
        for (int q = 0; q < 10; q++) {
            const float4 t = *(const float4*)&s[row][col + 4 * q]; // LDS.128
            v[4*q + 0] = t.x; v[4*q + 1] = t.y; v[4*q + 2] = t.z; v[4*q + 3] = t.w;
        }

        float acc[8];
#pragma unroll
        for (int r = 0; r < 8; r++) acc[r] = 0.0f;
#pragma unroll
        for (int j = 1; j < 39; j++) {
#pragma unroll
            for (int r = 0; r < 8; r++) {
                const int k = j - 1 - r;
                if (k >= 0 && k < 31) acc[r] = fmaf(w[k], v[j], acc[r]);
            }
        }

        uint4 u;
        u.x = h2u(__floats2half2_rn(acc[0], acc[1]));
        u.y = h2u(__floats2half2_rn(acc[2], acc[3]));
        u.z = h2u(__floats2half2_rn(acc[4], acc[5]));
        u.w = h2u(__floats2half2_rn(acc[6], acc[7]));

        void* dst = (__half*)g_temp2 + ((size_t)blockIdx.x * 8 + row) * Wd + col;
        asm volatile("st.global.L2::cache_hint.v4.b32 [%0], {%1,%2,%3,%4}, %5;"
                     :: "l"(dst), "r"(u.x), "r"(u.y), "r"(u.z), "r"(u.w), "l"(pol)
                     : "memory");
    }
}

// ---------------------------------------------------------------------------
// K2: vertical blur + fused epilogue, smem-staged (R14 config).
// Block = 16 out rows x 512 cols; stage rows [y0-15, y0+30] into smem.
// out stores carry an evict-first hint.
// ---------------------------------------------------------------------------
static constexpr int SROWS = 46;

__global__ void __launch_bounds__(256) k_vfinal(const float2* __restrict__ ins2,
                                                float2* __restrict__ out2) {
    const float w[31] = GW_LIST;
    __shared__ __align__(16) __half2 s2[SROWS][256];   // 47104 B

    const int tid = threadIdx.x;
    const int y0  = blockIdx.x * 16;
    const int z   = blockIdx.y;
    const size_t base = (size_t)z * (Hd * 256) + tid;   // half2/float2 units

    // ---- stage 46 rows of temp into smem (12 independent uint4 loads) ----
    const __half* tp = (const __half*)g_temp2 + (size_t)z * (Hd * Wd);
#pragma unroll
    for (int it = 0; it < 12; it++) {
        const int c = tid + it * 256;          // uint4 chunk id, 64 per row
        if (c < SROWS * 64) {
            const int m   = c >> 6;
            const int col = c & 63;            // uint4 within row
            const int yy  = y0 + m - 15;
            uint4 val = make_uint4(0u, 0u, 0u, 0u);
            if (yy >= 0 && yy < Hd)
                val = *(const uint4*)(tp + (size_t)yy * Wd + col * 8);
            *(uint4*)&s2[m][col * 4] = val;
        }
    }
    __syncthreads();

    // ---- vertical 31-tap conv from smem (conflict-free LDS.32) ----
    __half2 acc[16];
#pragma unroll
    for (int r = 0; r < 16; r++) acc[r] = __half2half2(__ushort_as_half(0));

#pragma unroll
    for (int m = 0; m < SROWS; m++) {
        const __half2 v = s2[m][tid];
#pragma unroll
        for (int r = 0; r < 16; r++) {
            const int k = m - r;
            if (k >= 0 && k < 31)
                acc[r] = __hfma2(v, __floats2half2_rn(w[k], w[k]), acc[r]);
        }
    }

    // ---- fused epilogue: out = clamp((1+ins) * 2^acc - 1) ----
    unsigned long long polw;
    asm("createpolicy.fractional.L2::evict_first.b64 %0, 1.0;" : "=l"(polw));
#pragma unroll
    for (int r = 0; r < 16; r++) {
        const float2 a  = __half22float2(acc[r]);
        const float2 iv = ins2[base + (size_t)(y0 + r) * 256];   // plain LDG
        const float e0 = fmaf(iv.x + 1.0f, ex2(a.x), -1.0f);
        const float e1 = fmaf(iv.y + 1.0f, ex2(a.y), -1.0f);
        const float o0 = fminf(fmaxf(e0, 0.0f), 1.0f);
        const float o1 = fminf(fmaxf(e1, 0.0f), 1.0f);
        void* dst = (void*)(out2 + base + (size_t)(y0 + r) * 256);
        asm volatile("st.global.L2::cache_hint.v2.b32 [%0], {%1,%2}, %3;"
                     :: "l"(dst), "r"(__float_as_uint(o0)), "r"(__float_as_uint(o1)),
                        "l"(polw) : "memory");
    }
}

// ---------------------------------------------------------------------------
extern "C" void kernel_launch(void* const* d_in, const int* in_sizes, int n_in,
                              void* d_out, int out_size) {
    (void)in_sizes; (void)n_in; (void)out_size;
    const float* bg  = (const float*)d_in[0];   // background
    const float* ins = (const float*)d_in[1];   // insatance
    float* out = (float*)d_out;

    k_hblur <<<NROWS / 8, 256>>>(bg, ins);
    k_vfinal<<<dim3(Hd / 16, NIMG), 256>>>((const float2*)ins, (float2*)out);
}

// round 16
// speedup vs baseline: 1.0882x; 1.0882x over previous
#include <cuda_runtime.h>
#include <cuda_fp16.h>

// retinex_synthesis: out = clip(expm1(log1p(ins) + blur(log1p(bg) - log1p(ins))), 0, 1)
// blur = depthwise 31x31 Gaussian (sigma=5), separable.
// Algebra:  blur(bg_log)-blur(ins_log) = blur(d2), d2 = log2(1+bg)-log2(1+ins)
//           out = (1+ins) * 2^blur(d2) - 1
// K1: horizontal 31-tap on d2 -> fp16 temp (evict-last stores). 4 rows/block
//     (R13 layout: conflict-light LDS, sector-perfect LDG).
// K2: vertical 31-tap in HFMA2, smem-staged 62-row slab (32 out rows/block,
//     dynamic smem 63.5 KB), plain out stores.

static constexpr int Wd    = 512;
static constexpr int Hd    = 512;
static constexpr int NIMG  = 48;                // B*C = 16*3
static constexpr int NPIX  = NIMG * Hd * Wd;    // 12,582,912
static constexpr int NROWS = NIMG * Hd;         // 24,576

__device__ __align__(16) __half2 g_temp2[NPIX / 2];   // 25.2 MB scratch

// Normalized 1D Gaussian, sigma=5, 31 taps (double-derived literals).
#define GW_LIST { \
    8.8805900e-4f, 1.5860940e-3f, 2.7217700e-3f, 4.4874400e-3f, 7.1084370e-3f, \
    1.0818768e-2f, 1.5820117e-2f, 2.2226435e-2f, 3.0002550e-2f, 3.8911210e-2f, \
    4.8486353e-2f, 5.8048703e-2f, 6.6771903e-2f, 7.3794366e-2f, 7.8357554e-2f, \
    7.9940482e-2f, \
    7.8357554e-2f, 7.3794366e-2f, 6.6771903e-2f, 5.8048703e-2f, 4.8486353e-2f, \
    3.8911210e-2f, 3.0002550e-2f, 2.2226435e-2f, 1.5820117e-2f, 1.0818768e-2f, \
    7.1084370e-3f, 4.4874400e-3f, 2.7217700e-3f, 1.5860940e-3f, 8.8805900e-4f }

__device__ __forceinline__ float ex2(float x) {        // MUFU.EX2
    float r; asm("ex2.approx.ftz.f32 %0, %1;" : "=f"(r) : "f"(x)); return r;
}
__device__ __forceinline__ float dlog2(float b, float i) {   // log2(1+b)-log2(1+i)
    return __log2f(1.0f + b) - __log2f(1.0f + i);
}
__device__ __forceinline__ unsigned h2u(__half2 h) {
    union { __half2 h; unsigned u; } c; c.h = h; return c.u;
}

// ---------------------------------------------------------------------------
// K1: horizontal blur of d2. One block = 4 rows (2048 floats). R13 version.
// ---------------------------------------------------------------------------
__global__ void __launch_bounds__(256) k_hblur(const float* __restrict__ bg,
                                               const float* __restrict__ ins) {
    const float w[31] = GW_LIST;
    __shared__ __align__(16) float s[4][544];   // [0..15]=0 | data | [528..543]=0

    const int tid = threadIdx.x;
    if (tid < 128) {
        const int r = tid >> 5, p = tid & 31;
        s[r][(p < 16) ? p : (512 + p)] = 0.0f;
    }

    const size_t gb = (size_t)blockIdx.x * 512;         // float4 units
    const float4* bg4 = (const float4*)bg;
    const float4* in4 = (const float4*)ins;

#pragma unroll
    for (int h = 0; h < 2; h++) {
        const int q = tid + h * 256;                    // f4 idx in block: 0..511
        const float4 b = __ldcs(bg4 + gb + q);          // bg: stream, evict-first
        const float4 i = in4[gb + q];                   // ins: plain
        const int row = q >> 7, col = (q & 127) * 4;
        *(float4*)&s[row][16 + col] =
            make_float4(dlog2(b.x, i.x), dlog2(b.y, i.y),
                        dlog2(b.z, i.z), dlog2(b.w, i.w));
    }
    __syncthreads();

    const int row = tid >> 6;             // 0..3
    const int col = (tid & 63) * 8;       // 0..504

    float v[40];
#pragma unroll
    for (int q = 0; q < 10; q++) {
        const float4 t = *(const float4*)&s[row][col + 4 * q];     // LDS.128
        v[4*q + 0] = t.x; v[4*q + 1] = t.y; v[4*q + 2] = t.z; v[4*q + 3] = t.w;
    }

    float acc[8];
#pragma unroll
    for (int r = 0; r < 8; r++) acc[r] = 0.0f;
#pragma unroll
    for (int j = 1; j < 39; j++) {
#pragma unroll
        for (int r = 0; r < 8; r++) {
            const int k = j - 1 - r;
            if (k >= 0 && k < 31) acc[r] = fmaf(w[k], v[j], acc[r]);
        }
    }

    uint4 u;
    u.x = h2u(__floats2half2_rn(acc[0], acc[1]));
    u.y = h2u(__floats2half2_rn(acc[2], acc[3]));
    u.z = h2u(__floats2half2_rn(acc[4], acc[5]));
    u.w = h2u(__floats2half2_rn(acc[6], acc[7]));

    void* dst = (__half*)g_temp2 + ((size_t)blockIdx.x * 4 + row) * Wd + col;
    unsigned long long pol;
    asm("createpolicy.fractional.L2::evict_last.b64 %0, 1.0;" : "=l"(pol));
    asm volatile("st.global.L2::cache_hint.v4.b32 [%0], {%1,%2,%3,%4}, %5;"
                 :: "l"(dst), "r"(u.x), "r"(u.y), "r"(u.z), "r"(u.w), "l"(pol)
                 : "memory");
}

// ---------------------------------------------------------------------------
// K2: vertical blur + fused epilogue, smem-staged, 32 out rows/block.
// Stage rows [y0-15, y0+46] (62 rows, zero-padded at edges) into dynamic smem,
// then HFMA2 conv from LDS. Thread = 2 adjacent cols x 32 rows.
// grid = (Hd/32, NIMG), 256 threads.
// ---------------------------------------------------------------------------
static constexpr int OUTR  = 32;
static constexpr int SROWS = OUTR + 30;               // 62
static constexpr int K2_SMEM = SROWS * 256 * 4;       // 63488 B (half2 words)

__global__ void __launch_bounds__(256) k_vfinal(const float2* __restrict__ ins2,
                                                float2* __restrict__ out2) {
    const float w[31] = GW_LIST;
    extern __shared__ __align__(16) __half2 s2[];     // [SROWS][256]

    const int tid = threadIdx.x;
    const int y0  = blockIdx.x * OUTR;
    const int z   = blockIdx.y;
    const size_t base = (size_t)z * (Hd * 256) + tid;  // half2/float2 units

    // ---- stage 62 rows of temp into smem (16 independent uint4 loads) ----
    const __half* tp = (const __half*)g_temp2 + (size_t)z * (Hd * Wd);
#pragma unroll
    for (int it = 0; it < 16; it++) {
        const int c = tid + it * 256;          // uint4 chunk id, 64 per row
        if (c < SROWS * 64) {
            const int m   = c >> 6;
            const int col = c & 63;            // uint4 within row
            const int yy  = y0 + m - 15;
            uint4 val = make_uint4(0u, 0u, 0u, 0u);
            if (yy >= 0 && yy < Hd)
                val = *(const uint4*)(tp + (size_t)yy * Wd + col * 8);
            *(uint4*)&s2[m * 256 + col * 4] = val;
        }
    }
    __syncthreads();

    // ---- vertical 31-tap conv from smem (conflict-free LDS.32) ----
    __half2 acc[OUTR];
#pragma unroll
    for (int r = 0; r < OUTR; r++) acc[r] = __half2half2(__ushort_as_half(0));

#pragma unroll
    for (int m = 0; m < SROWS; m++) {
        const __half2 v = s2[m * 256 + tid];
#pragma unroll
        for (int r = 0; r < OUTR; r++) {
            const int k = m - r;
            if (k >= 0 && k < 31)
                acc[r] = __hfma2(v, __floats2half2_rn(w[k], w[k]), acc[r]);
        }
    }

    // ---- fused epilogue: out = clamp((1+ins) * 2^acc - 1) ----
#pragma unroll
    for (int r = 0; r < OUTR; r++) {
        const float2 a  = __half22float2(acc[r]);
        const float2 iv = ins2[base + (size_t)(y0 + r) * 256];   // plain LDG
        const float e0 = fmaf(iv.x + 1.0f, ex2(a.x), -1.0f);
        const float e1 = fmaf(iv.y + 1.0f, ex2(a.y), -1.0f);
        float2 o;
        o.x = fminf(fmaxf(e0, 0.0f), 1.0f);
        o.y = fminf(fmaxf(e1, 0.0f), 1.0f);
        out2[base + (size_t)(y0 + r) * 256] = o;
    }
}

// ---------------------------------------------------------------------------
extern "C" void kernel_launch(void* const* d_in, const int* in_sizes, int n_in,
                              void* d_out, int out_size) {
    (void)in_sizes; (void)n_in; (void)out_size;
    const float* bg  = (const float*)d_in[0];   // background
    const float* ins = (const float*)d_in[1];   // insatance
    float* out = (float*)d_out;

    cudaFuncSetAttribute(k_vfinal, cudaFuncAttributeMaxDynamicSharedMemorySize,
                         K2_SMEM);

    k_hblur <<<NROWS / 4, 256>>>(bg, ins);
    k_vfinal<<<dim3(Hd / OUTR, NIMG), 256, K2_SMEM>>>((const float2*)ins,
                                                      (float2*)out);
}